// round 11
// baseline (speedup 1.0000x reference)
#include <cuda_runtime.h>
#include <cuda_bf16.h>
#include <cstdint>

// LinearRationalSpline forward — persistent, cp.async.bulk double-buffered,
// dynamic work-stealing with self-normalizing ticket counter (single kernel,
// no reset launch: each launch consumes exactly tiles_full + gridDim tickets,
// so tile = ticket % span is launch-local and deterministic).
// inputs:  d_in[0] = inputs        [16384*64]        float32
//          d_in[1] = params_unnorm [16384*64, 63]    float32
// output:  d_out = concat(outputs, logabsdet) [2 * n] float32

#define KB  16
#define PPE 63
#define TPB 128
#define GRID_CTAS 444                       // 148 SMs * 3 CTAs

#define TILE_PAR_BYTES (TPB * PPE * 4)      // 32256 (16B multiple)
#define TILE_X_BYTES   (TPB * 4)            // 512
#define SLOT_BYTES     (TILE_PAR_BYTES + TILE_X_BYTES)   // 32768
#define SMEM_BYTES     (2 * SLOT_BYTES + 32)             // + mbarriers + tile ids

__device__ unsigned int g_tile_ctr = 0u;

__device__ __forceinline__ float softplus_f(float x) {
    return fmaxf(x, 0.0f) + log1pf(__expf(-fabsf(x)));
}

__device__ __forceinline__ void mbar_init(uint32_t mbar, uint32_t cnt) {
    asm volatile("mbarrier.init.shared.b64 [%0], %1;" :: "r"(mbar), "r"(cnt) : "memory");
}

__device__ __forceinline__ void mbar_wait(uint32_t mbar, uint32_t parity) {
    uint32_t done;
    asm volatile(
        "{\n\t.reg .pred p;\n\t"
        "mbarrier.try_wait.parity.acquire.cta.shared::cta.b64 p, [%1], %2;\n\t"
        "selp.b32 %0, 1, 0, p;\n\t}"
        : "=r"(done) : "r"(mbar), "r"(parity) : "memory");
    if (!done) {
        asm volatile(
            "{\n\t.reg .pred P1;\n\t"
            "W_%=:\n\t"
            "mbarrier.try_wait.parity.acquire.cta.shared::cta.b64 P1, [%0], %1, 0x989680;\n\t"
            "@P1 bra.uni D_%=;\n\t"
            "bra.uni W_%=;\n\t"
            "D_%=:\n\t}"
            :: "r"(mbar), "r"(parity) : "memory");
    }
}

// Thread 0 only: arm barrier and issue two bulk copies (params + x) into slot.
__device__ __forceinline__ void bulk_prefetch(int tile,
                                              const float* __restrict__ par,
                                              const float* __restrict__ inp,
                                              uint32_t slot_addr, uint32_t mbar)
{
    asm volatile("mbarrier.arrive.expect_tx.shared.b64 _, [%0], %1;"
                 :: "r"(mbar), "r"((uint32_t)SLOT_BYTES) : "memory");
    const void* gp = par + (size_t)tile * TPB * PPE;    // tile*32256 B -> 16B aligned
    asm volatile("cp.async.bulk.shared::cta.global.mbarrier::complete_tx::bytes "
                 "[%0], [%1], %2, [%3];"
                 :: "r"(slot_addr), "l"(gp), "r"((uint32_t)TILE_PAR_BYTES), "r"(mbar)
                 : "memory");
    const void* gx = inp + (size_t)tile * TPB;
    asm volatile("cp.async.bulk.shared::cta.global.mbarrier::complete_tx::bytes "
                 "[%0], [%1], %2, [%3];"
                 :: "r"(slot_addr + TILE_PAR_BYTES), "l"(gx), "r"((uint32_t)TILE_X_BYTES), "r"(mbar)
                 : "memory");
}

__device__ __forceinline__ void lrs_compute(const float* __restrict__ p, float x,
                                            int e, int n, float* __restrict__ out)
{
    const float BOUND = 3.0f;
    const float MD    = 0.001f;
    const float EPSV  = 1e-6f;

    // softmax numerators
    float ew[KB], eh[KB];
    float sw = 0.0f, sh = 0.0f;
    #pragma unroll
    for (int i = 0; i < KB; i++) { float v = __expf(p[i]);      ew[i] = v; sw += v; }
    #pragma unroll
    for (int i = 0; i < KB; i++) { float v = __expf(p[KB + i]); eh[i] = v; sh += v; }

    const float scw = __fdividef(5.904f, sw);   // 6*(1 - 16*0.001)
    const float sch = __fdividef(5.904f, sh);

    // fused knot-gen + bin-search + edge-select (knots strictly increasing)
    float cw = 0.0f, ch = 0.0f;
    int   idx = 0;
    float cwl = -BOUND, chl = -BOUND, cwr = BOUND, chr = BOUND;
    bool  done = false;
    #pragma unroll
    for (int i = 0; i < KB; i++) {
        cw += ew[i];
        ch += eh[i];
        float off = -BOUND + 0.006f * (float)(i + 1);
        float kw = (i == KB - 1) ? BOUND : fmaf(cw, scw, off);
        float kh = (i == KB - 1) ? BOUND : fmaf(ch, sch, off);
        bool pred = (i < KB - 1) && (kw + EPSV <= x);
        if (pred)        { idx++; cwl = kw; chl = kh; }
        else if (!done)  { cwr = kw; chr = kh; done = true; }
    }

    const float wsel = cwr - cwl;
    const float hsel = chr - chl;

    // derivatives at surrounding knots (2 softplus only; safe neighbor reads)
    float dl, dr;
    {
        float dls = MD + softplus_f(p[2*KB + idx - 1]);
        float drs = MD + softplus_f(p[2*KB + idx]);
        dl = (idx == 0)      ? (1.0f - MD) : dls;
        dr = (idx == KB - 1) ? (1.0f - MD) : drs;
    }

    // lambda (selected only)
    float lamraw = p[3*KB - 1 + idx];
    float sig = __fdividef(1.0f, 1.0f + __expf(-lamraw));
    float lam = fmaf(0.95f, sig, 0.025f);

    // rational-linear spline
    float wb  = sqrtf(__fdividef(dl, dr));
    float lwb = lam * wb;
    float wc  = __fdividef(fmaf(lam, dl, (wb - lwb) * dr) * wsel, hsel);

    float ya = chl;
    float yb = chr;
    float l1 = 1.0f - lam;
    float yc = __fdividef(fmaf(lwb, yb, l1 * ya), l1 + lwb);

    float theta  = __fdividef(x - cwl, wsel);
    bool  ind    = theta <= lam;
    float ltheta = lam - theta;

    float wcyc      = wc * yc;
    float wcyctheta = wcyc * theta;
    float num = ind ? fmaf(ya, ltheta, wcyctheta)
                    : (wcyc - wcyctheta) - (wb * yb) * ltheta;
    float wctheta = wc * theta;
    float den = ind ? (wctheta + ltheta)
                    : (wc - wctheta) - wb * ltheta;

    float outv = __fdividef(num, den);

    float dnum = __fdividef(wc * (ind ? lam * (yc - ya) : (wb - lwb) * (yb - yc)), wsel);
    float lad  = __logf(dnum) - 2.0f * __logf(fabsf(den));

    bool outside = (x < -BOUND) || (x > BOUND);
    out[e]     = outside ? x    : outv;
    out[n + e] = outside ? 0.0f : lad;
}

__global__ __launch_bounds__(TPB)
void lrs_kernel(const float* __restrict__ inp,
                const float* __restrict__ par,
                float* __restrict__ out,
                int n)
{
    extern __shared__ unsigned char smem_raw[];
    float* slotf0 = reinterpret_cast<float*>(smem_raw);
    float* slotf1 = reinterpret_cast<float*>(smem_raw + SLOT_BYTES);
    const uint32_t sbase  = (uint32_t)__cvta_generic_to_shared(smem_raw);
    const uint32_t slot_a0 = sbase;
    const uint32_t slot_a1 = sbase + SLOT_BYTES;
    const uint32_t mbar0   = sbase + 2 * SLOT_BYTES;
    const uint32_t mbar1   = mbar0 + 8;
    volatile int* stid = reinterpret_cast<volatile int*>(smem_raw + 2 * SLOT_BYTES + 16);

    const int tiles_full = n / TPB;
    // Each launch consumes exactly (tiles_full + gridDim.x) tickets:
    //   one per processed tile + exactly one stop-ticket (>= tiles_full) per CTA.
    // So launch-local tile id = ticket % span, without ever resetting the counter.
    const unsigned int span = (unsigned int)(tiles_full + gridDim.x);

    if (threadIdx.x == 0) {
        mbar_init(mbar0, 1);
        mbar_init(mbar1, 1);
        int t0 = (int)(atomicAdd(&g_tile_ctr, 1u) % span);
        stid[0] = t0;
        if (t0 < tiles_full)
            bulk_prefetch(t0, par, inp, slot_a0, mbar0);
    }
    __syncthreads();

    int cur = 0, ph0 = 0, ph1 = 0;
    for (;;) {
        const int tcur = stid[cur];
        if (tcur >= tiles_full) break;

        // steal next tile and prefetch into the other slot
        if (threadIdx.x == 0) {
            int tn = (int)(atomicAdd(&g_tile_ctr, 1u) % span);
            stid[cur ^ 1] = tn;
            if (tn < tiles_full)
                bulk_prefetch(tn, par, inp, cur ? slot_a0 : slot_a1, cur ? mbar0 : mbar1);
        }

        // wait current slot
        if (cur) { mbar_wait(mbar1, ph1); ph1 ^= 1; }
        else     { mbar_wait(mbar0, ph0); ph0 ^= 1; }

        const float* sl = cur ? slotf1 : slotf0;
        const float* p  = sl + threadIdx.x * PPE;        // stride 63 -> conflict-free
        const float  x  = sl[TPB * PPE + threadIdx.x];
        const int    e  = tcur * TPB + threadIdx.x;

        lrs_compute(p, x, e, n, out);

        __syncthreads();   // reads done; stid[cur^1] visible to all
        cur ^= 1;
    }

    // ragged tail (n % TPB elements), handled by block 0 straight from global
    if (blockIdx.x == 0) {
        int e = tiles_full * TPB + threadIdx.x;
        if (e < n) {
            float pr[PPE];
            const float* g = par + (size_t)e * PPE;
            #pragma unroll
            for (int i = 0; i < PPE; i++) pr[i] = g[i];
            lrs_compute(pr, inp[e], e, n, out);
        }
    }
}

extern "C" void kernel_launch(void* const* d_in, const int* in_sizes, int n_in,
                              void* d_out, int out_size) {
    const float* inp = (const float*)d_in[0];
    const float* par = (const float*)d_in[1];
    float* out = (float*)d_out;
    int n = in_sizes[0];

    cudaFuncSetAttribute(lrs_kernel, cudaFuncAttributeMaxDynamicSharedMemorySize, SMEM_BYTES);

    int ntiles = (n + TPB - 1) / TPB;
    int grid = GRID_CTAS < ntiles ? GRID_CTAS : (ntiles > 0 ? ntiles : 1);
    lrs_kernel<<<grid, TPB, SMEM_BYTES>>>(inp, par, out, n);
}

// round 13
// speedup vs baseline: 1.1018x; 1.1018x over previous
#include <cuda_runtime.h>
#include <cuda_bf16.h>
#include <cstdint>

// LinearRationalSpline forward — persistent, cp.async.bulk double-buffered,
// dynamic work-stealing; single kernel with end-of-launch counter self-reset
// (last CTA to finish zeroes the ticket counter; exact ticket accounting
// guarantees no CTA touches it afterward).
// inputs:  d_in[0] = inputs        [16384*64]        float32
//          d_in[1] = params_unnorm [16384*64, 63]    float32
// output:  d_out = concat(outputs, logabsdet) [2 * n] float32

#define KB  16
#define PPE 63
#define TPB 128
#define GRID_CTAS 444                       // 148 SMs * 3 CTAs

#define TILE_PAR_BYTES (TPB * PPE * 4)      // 32256 (16B multiple)
#define TILE_X_BYTES   (TPB * 4)            // 512
#define SLOT_BYTES     (TILE_PAR_BYTES + TILE_X_BYTES)   // 32768
#define SMEM_BYTES     (2 * SLOT_BYTES + 32)             // + mbarriers + tile ids

__device__ unsigned int g_tile_ctr = 0u;
__device__ unsigned int g_done_ctr = 0u;

__device__ __forceinline__ float softplus_f(float x) {
    return fmaxf(x, 0.0f) + log1pf(__expf(-fabsf(x)));
}

__device__ __forceinline__ void mbar_init(uint32_t mbar, uint32_t cnt) {
    asm volatile("mbarrier.init.shared.b64 [%0], %1;" :: "r"(mbar), "r"(cnt) : "memory");
}

__device__ __forceinline__ void mbar_wait(uint32_t mbar, uint32_t parity) {
    uint32_t done;
    asm volatile(
        "{\n\t.reg .pred p;\n\t"
        "mbarrier.try_wait.parity.acquire.cta.shared::cta.b64 p, [%1], %2;\n\t"
        "selp.b32 %0, 1, 0, p;\n\t}"
        : "=r"(done) : "r"(mbar), "r"(parity) : "memory");
    if (!done) {
        asm volatile(
            "{\n\t.reg .pred P1;\n\t"
            "W_%=:\n\t"
            "mbarrier.try_wait.parity.acquire.cta.shared::cta.b64 P1, [%0], %1, 0x989680;\n\t"
            "@P1 bra.uni D_%=;\n\t"
            "bra.uni W_%=;\n\t"
            "D_%=:\n\t}"
            :: "r"(mbar), "r"(parity) : "memory");
    }
}

// Thread 0 only: arm barrier and issue two bulk copies (params + x) into slot.
__device__ __forceinline__ void bulk_prefetch(int tile,
                                              const float* __restrict__ par,
                                              const float* __restrict__ inp,
                                              uint32_t slot_addr, uint32_t mbar)
{
    asm volatile("mbarrier.arrive.expect_tx.shared.b64 _, [%0], %1;"
                 :: "r"(mbar), "r"((uint32_t)SLOT_BYTES) : "memory");
    const void* gp = par + (size_t)tile * TPB * PPE;    // tile*32256 B -> 16B aligned
    asm volatile("cp.async.bulk.shared::cta.global.mbarrier::complete_tx::bytes "
                 "[%0], [%1], %2, [%3];"
                 :: "r"(slot_addr), "l"(gp), "r"((uint32_t)TILE_PAR_BYTES), "r"(mbar)
                 : "memory");
    const void* gx = inp + (size_t)tile * TPB;
    asm volatile("cp.async.bulk.shared::cta.global.mbarrier::complete_tx::bytes "
                 "[%0], [%1], %2, [%3];"
                 :: "r"(slot_addr + TILE_PAR_BYTES), "l"(gx), "r"((uint32_t)TILE_X_BYTES), "r"(mbar)
                 : "memory");
}

__device__ __forceinline__ void lrs_compute(const float* __restrict__ p, float x,
                                            int e, int n, float* __restrict__ out)
{
    const float BOUND = 3.0f;
    const float MD    = 0.001f;
    const float EPSV  = 1e-6f;

    // softmax numerators
    float ew[KB], eh[KB];
    float sw = 0.0f, sh = 0.0f;
    #pragma unroll
    for (int i = 0; i < KB; i++) { float v = __expf(p[i]);      ew[i] = v; sw += v; }
    #pragma unroll
    for (int i = 0; i < KB; i++) { float v = __expf(p[KB + i]); eh[i] = v; sh += v; }

    const float scw = __fdividef(5.904f, sw);   // 6*(1 - 16*0.001)
    const float sch = __fdividef(5.904f, sh);

    // fused knot-gen + bin-search + edge-select (knots strictly increasing)
    float cw = 0.0f, ch = 0.0f;
    int   idx = 0;
    float cwl = -BOUND, chl = -BOUND, cwr = BOUND, chr = BOUND;
    bool  done = false;
    #pragma unroll
    for (int i = 0; i < KB; i++) {
        cw += ew[i];
        ch += eh[i];
        float off = -BOUND + 0.006f * (float)(i + 1);
        float kw = (i == KB - 1) ? BOUND : fmaf(cw, scw, off);
        float kh = (i == KB - 1) ? BOUND : fmaf(ch, sch, off);
        bool pred = (i < KB - 1) && (kw + EPSV <= x);
        if (pred)        { idx++; cwl = kw; chl = kh; }
        else if (!done)  { cwr = kw; chr = kh; done = true; }
    }

    const float wsel = cwr - cwl;
    const float hsel = chr - chl;

    // derivatives at surrounding knots (2 softplus only; safe neighbor reads)
    float dl, dr;
    {
        float dls = MD + softplus_f(p[2*KB + idx - 1]);
        float drs = MD + softplus_f(p[2*KB + idx]);
        dl = (idx == 0)      ? (1.0f - MD) : dls;
        dr = (idx == KB - 1) ? (1.0f - MD) : drs;
    }

    // lambda (selected only)
    float lamraw = p[3*KB - 1 + idx];
    float sig = __fdividef(1.0f, 1.0f + __expf(-lamraw));
    float lam = fmaf(0.95f, sig, 0.025f);

    // rational-linear spline
    float wb  = sqrtf(__fdividef(dl, dr));
    float lwb = lam * wb;
    float wc  = __fdividef(fmaf(lam, dl, (wb - lwb) * dr) * wsel, hsel);

    float ya = chl;
    float yb = chr;
    float l1 = 1.0f - lam;
    float yc = __fdividef(fmaf(lwb, yb, l1 * ya), l1 + lwb);

    float theta  = __fdividef(x - cwl, wsel);
    bool  ind    = theta <= lam;
    float ltheta = lam - theta;

    float wcyc      = wc * yc;
    float wcyctheta = wcyc * theta;
    float num = ind ? fmaf(ya, ltheta, wcyctheta)
                    : (wcyc - wcyctheta) - (wb * yb) * ltheta;
    float wctheta = wc * theta;
    float den = ind ? (wctheta + ltheta)
                    : (wc - wctheta) - wb * ltheta;

    float outv = __fdividef(num, den);

    float dnum = __fdividef(wc * (ind ? lam * (yc - ya) : (wb - lwb) * (yb - yc)), wsel);
    float lad  = __logf(dnum) - 2.0f * __logf(fabsf(den));

    bool outside = (x < -BOUND) || (x > BOUND);
    out[e]     = outside ? x    : outv;
    out[n + e] = outside ? 0.0f : lad;
}

__global__ __launch_bounds__(TPB)
void lrs_kernel(const float* __restrict__ inp,
                const float* __restrict__ par,
                float* __restrict__ out,
                int n)
{
    extern __shared__ unsigned char smem_raw[];
    float* slotf0 = reinterpret_cast<float*>(smem_raw);
    float* slotf1 = reinterpret_cast<float*>(smem_raw + SLOT_BYTES);
    const uint32_t sbase  = (uint32_t)__cvta_generic_to_shared(smem_raw);
    const uint32_t slot_a0 = sbase;
    const uint32_t slot_a1 = sbase + SLOT_BYTES;
    const uint32_t mbar0   = sbase + 2 * SLOT_BYTES;
    const uint32_t mbar1   = mbar0 + 8;
    volatile int* stid = reinterpret_cast<volatile int*>(smem_raw + 2 * SLOT_BYTES + 16);

    const int tiles_full = n / TPB;

    if (threadIdx.x == 0) {
        mbar_init(mbar0, 1);
        mbar_init(mbar1, 1);
        int t0 = (int)atomicAdd(&g_tile_ctr, 1u);
        stid[0] = t0;
        if (t0 < tiles_full)
            bulk_prefetch(t0, par, inp, slot_a0, mbar0);
    }
    __syncthreads();

    int cur = 0, ph0 = 0, ph1 = 0;
    for (;;) {
        const int tcur = stid[cur];
        if (tcur >= tiles_full) break;

        // steal next tile and prefetch into the other slot (bare atomicAdd ->
        // prefetch path: keep it free of any extra arithmetic, it gates DRAM refill)
        if (threadIdx.x == 0) {
            int tn = (int)atomicAdd(&g_tile_ctr, 1u);
            stid[cur ^ 1] = tn;
            if (tn < tiles_full)
                bulk_prefetch(tn, par, inp, cur ? slot_a0 : slot_a1, cur ? mbar0 : mbar1);
        }

        // wait current slot
        if (cur) { mbar_wait(mbar1, ph1); ph1 ^= 1; }
        else     { mbar_wait(mbar0, ph0); ph0 ^= 1; }

        const float* sl = cur ? slotf1 : slotf0;
        const float* p  = sl + threadIdx.x * PPE;        // stride 63 -> conflict-free
        const float  x  = sl[TPB * PPE + threadIdx.x];
        const int    e  = tcur * TPB + threadIdx.x;

        lrs_compute(p, x, e, n, out);

        __syncthreads();   // reads done; stid[cur^1] visible to all
        cur ^= 1;
    }

    // ragged tail (n % TPB elements), handled by block 0 straight from global
    if (blockIdx.x == 0) {
        int e = tiles_full * TPB + threadIdx.x;
        if (e < n) {
            float pr[PPE];
            const float* g = par + (size_t)e * PPE;
            #pragma unroll
            for (int i = 0; i < PPE; i++) pr[i] = g[i];
            lrs_compute(pr, inp[e], e, n, out);
        }
    }

    // ---- end-of-launch self-reset ----
    // Exact accounting: every CTA draws exactly one stop ticket (>= tiles_full),
    // so total tickets per launch = tiles_full + gridDim.x. When the LAST CTA
    // arrives here, all stop tickets have been drawn -> no further atomicAdds on
    // g_tile_ctr this launch. That CTA resets both counters for the next replay.
    __syncthreads();
    if (threadIdx.x == 0) {
        __threadfence();
        unsigned int d = atomicAdd(&g_done_ctr, 1u);
        if (d == gridDim.x - 1u) {
            atomicExch(&g_tile_ctr, 0u);
            atomicExch(&g_done_ctr, 0u);
        }
    }
}

extern "C" void kernel_launch(void* const* d_in, const int* in_sizes, int n_in,
                              void* d_out, int out_size) {
    const float* inp = (const float*)d_in[0];
    const float* par = (const float*)d_in[1];
    float* out = (float*)d_out;
    int n = in_sizes[0];

    cudaFuncSetAttribute(lrs_kernel, cudaFuncAttributeMaxDynamicSharedMemorySize, SMEM_BYTES);

    int ntiles = (n + TPB - 1) / TPB;
    int grid = GRID_CTAS < ntiles ? GRID_CTAS : (ntiles > 0 ? ntiles : 1);
    lrs_kernel<<<grid, TPB, SMEM_BYTES>>>(inp, par, out, n);
}

// round 14
// speedup vs baseline: 1.1185x; 1.0152x over previous
#include <cuda_runtime.h>
#include <cuda_bf16.h>
#include <cstdint>

// LinearRationalSpline forward — persistent, cp.async.bulk double-buffered,
// dynamic work-stealing, fine-grained tiles: TPB=64, 16KB slots, 6 CTAs/SM
// (more independent DRAM streams -> smoother queue occupancy).
// Single kernel with end-of-launch counter self-reset.
// inputs:  d_in[0] = inputs        [16384*64]        float32
//          d_in[1] = params_unnorm [16384*64, 63]    float32
// output:  d_out = concat(outputs, logabsdet) [2 * n] float32

#define KB  16
#define PPE 63
#define TPB 64
#define GRID_CTAS 888                       // 148 SMs * 6 CTAs

#define TILE_PAR_BYTES (TPB * PPE * 4)      // 16128 (16B multiple)
#define TILE_X_BYTES   (TPB * 4)            // 256
#define SLOT_BYTES     (TILE_PAR_BYTES + TILE_X_BYTES)   // 16384
#define SMEM_BYTES     (2 * SLOT_BYTES + 32)             // + mbarriers + tile ids

__device__ unsigned int g_tile_ctr = 0u;
__device__ unsigned int g_done_ctr = 0u;

__device__ __forceinline__ float softplus_f(float x) {
    return fmaxf(x, 0.0f) + log1pf(__expf(-fabsf(x)));
}

__device__ __forceinline__ void mbar_init(uint32_t mbar, uint32_t cnt) {
    asm volatile("mbarrier.init.shared.b64 [%0], %1;" :: "r"(mbar), "r"(cnt) : "memory");
}

__device__ __forceinline__ void mbar_wait(uint32_t mbar, uint32_t parity) {
    uint32_t done;
    asm volatile(
        "{\n\t.reg .pred p;\n\t"
        "mbarrier.try_wait.parity.acquire.cta.shared::cta.b64 p, [%1], %2;\n\t"
        "selp.b32 %0, 1, 0, p;\n\t}"
        : "=r"(done) : "r"(mbar), "r"(parity) : "memory");
    if (!done) {
        asm volatile(
            "{\n\t.reg .pred P1;\n\t"
            "W_%=:\n\t"
            "mbarrier.try_wait.parity.acquire.cta.shared::cta.b64 P1, [%0], %1, 0x989680;\n\t"
            "@P1 bra.uni D_%=;\n\t"
            "bra.uni W_%=;\n\t"
            "D_%=:\n\t}"
            :: "r"(mbar), "r"(parity) : "memory");
    }
}

// Thread 0 only: arm barrier and issue two bulk copies (params + x) into slot.
__device__ __forceinline__ void bulk_prefetch(int tile,
                                              const float* __restrict__ par,
                                              const float* __restrict__ inp,
                                              uint32_t slot_addr, uint32_t mbar)
{
    asm volatile("mbarrier.arrive.expect_tx.shared.b64 _, [%0], %1;"
                 :: "r"(mbar), "r"((uint32_t)SLOT_BYTES) : "memory");
    const void* gp = par + (size_t)tile * TPB * PPE;    // tile*16128 B -> 16B aligned
    asm volatile("cp.async.bulk.shared::cta.global.mbarrier::complete_tx::bytes "
                 "[%0], [%1], %2, [%3];"
                 :: "r"(slot_addr), "l"(gp), "r"((uint32_t)TILE_PAR_BYTES), "r"(mbar)
                 : "memory");
    const void* gx = inp + (size_t)tile * TPB;
    asm volatile("cp.async.bulk.shared::cta.global.mbarrier::complete_tx::bytes "
                 "[%0], [%1], %2, [%3];"
                 :: "r"(slot_addr + TILE_PAR_BYTES), "l"(gx), "r"((uint32_t)TILE_X_BYTES), "r"(mbar)
                 : "memory");
}

__device__ __forceinline__ void lrs_compute(const float* __restrict__ p, float x,
                                            int e, int n, float* __restrict__ out)
{
    const float BOUND = 3.0f;
    const float MD    = 0.001f;
    const float EPSV  = 1e-6f;

    // softmax numerators
    float ew[KB], eh[KB];
    float sw = 0.0f, sh = 0.0f;
    #pragma unroll
    for (int i = 0; i < KB; i++) { float v = __expf(p[i]);      ew[i] = v; sw += v; }
    #pragma unroll
    for (int i = 0; i < KB; i++) { float v = __expf(p[KB + i]); eh[i] = v; sh += v; }

    const float scw = __fdividef(5.904f, sw);   // 6*(1 - 16*0.001)
    const float sch = __fdividef(5.904f, sh);

    // fused knot-gen + bin-search + edge-select (knots strictly increasing)
    float cw = 0.0f, ch = 0.0f;
    int   idx = 0;
    float cwl = -BOUND, chl = -BOUND, cwr = BOUND, chr = BOUND;
    bool  done = false;
    #pragma unroll
    for (int i = 0; i < KB; i++) {
        cw += ew[i];
        ch += eh[i];
        float off = -BOUND + 0.006f * (float)(i + 1);
        float kw = (i == KB - 1) ? BOUND : fmaf(cw, scw, off);
        float kh = (i == KB - 1) ? BOUND : fmaf(ch, sch, off);
        bool pred = (i < KB - 1) && (kw + EPSV <= x);
        if (pred)        { idx++; cwl = kw; chl = kh; }
        else if (!done)  { cwr = kw; chr = kh; done = true; }
    }

    const float wsel = cwr - cwl;
    const float hsel = chr - chl;

    // derivatives at surrounding knots (2 softplus only; safe neighbor reads)
    float dl, dr;
    {
        float dls = MD + softplus_f(p[2*KB + idx - 1]);
        float drs = MD + softplus_f(p[2*KB + idx]);
        dl = (idx == 0)      ? (1.0f - MD) : dls;
        dr = (idx == KB - 1) ? (1.0f - MD) : drs;
    }

    // lambda (selected only)
    float lamraw = p[3*KB - 1 + idx];
    float sig = __fdividef(1.0f, 1.0f + __expf(-lamraw));
    float lam = fmaf(0.95f, sig, 0.025f);

    // rational-linear spline
    float wb  = sqrtf(__fdividef(dl, dr));
    float lwb = lam * wb;
    float wc  = __fdividef(fmaf(lam, dl, (wb - lwb) * dr) * wsel, hsel);

    float ya = chl;
    float yb = chr;
    float l1 = 1.0f - lam;
    float yc = __fdividef(fmaf(lwb, yb, l1 * ya), l1 + lwb);

    float theta  = __fdividef(x - cwl, wsel);
    bool  ind    = theta <= lam;
    float ltheta = lam - theta;

    float wcyc      = wc * yc;
    float wcyctheta = wcyc * theta;
    float num = ind ? fmaf(ya, ltheta, wcyctheta)
                    : (wcyc - wcyctheta) - (wb * yb) * ltheta;
    float wctheta = wc * theta;
    float den = ind ? (wctheta + ltheta)
                    : (wc - wctheta) - wb * ltheta;

    float outv = __fdividef(num, den);

    float dnum = __fdividef(wc * (ind ? lam * (yc - ya) : (wb - lwb) * (yb - yc)), wsel);
    float lad  = __logf(dnum) - 2.0f * __logf(fabsf(den));

    bool outside = (x < -BOUND) || (x > BOUND);
    out[e]     = outside ? x    : outv;
    out[n + e] = outside ? 0.0f : lad;
}

__global__ __launch_bounds__(TPB)
void lrs_kernel(const float* __restrict__ inp,
                const float* __restrict__ par,
                float* __restrict__ out,
                int n)
{
    extern __shared__ unsigned char smem_raw[];
    float* slotf0 = reinterpret_cast<float*>(smem_raw);
    float* slotf1 = reinterpret_cast<float*>(smem_raw + SLOT_BYTES);
    const uint32_t sbase  = (uint32_t)__cvta_generic_to_shared(smem_raw);
    const uint32_t slot_a0 = sbase;
    const uint32_t slot_a1 = sbase + SLOT_BYTES;
    const uint32_t mbar0   = sbase + 2 * SLOT_BYTES;
    const uint32_t mbar1   = mbar0 + 8;
    volatile int* stid = reinterpret_cast<volatile int*>(smem_raw + 2 * SLOT_BYTES + 16);

    const int tiles_full = n / TPB;

    if (threadIdx.x == 0) {
        mbar_init(mbar0, 1);
        mbar_init(mbar1, 1);
        int t0 = (int)atomicAdd(&g_tile_ctr, 1u);
        stid[0] = t0;
        if (t0 < tiles_full)
            bulk_prefetch(t0, par, inp, slot_a0, mbar0);
    }
    __syncthreads();

    int cur = 0, ph0 = 0, ph1 = 0;
    for (;;) {
        const int tcur = stid[cur];
        if (tcur >= tiles_full) break;

        // steal next tile and prefetch into the other slot (bare atomicAdd ->
        // prefetch path: keep it free of extra arithmetic, it gates DRAM refill)
        if (threadIdx.x == 0) {
            int tn = (int)atomicAdd(&g_tile_ctr, 1u);
            stid[cur ^ 1] = tn;
            if (tn < tiles_full)
                bulk_prefetch(tn, par, inp, cur ? slot_a0 : slot_a1, cur ? mbar0 : mbar1);
        }

        // wait current slot
        if (cur) { mbar_wait(mbar1, ph1); ph1 ^= 1; }
        else     { mbar_wait(mbar0, ph0); ph0 ^= 1; }

        const float* sl = cur ? slotf1 : slotf0;
        const float* p  = sl + threadIdx.x * PPE;        // stride 63 -> conflict-free
        const float  x  = sl[TPB * PPE + threadIdx.x];
        const int    e  = tcur * TPB + threadIdx.x;

        lrs_compute(p, x, e, n, out);

        __syncthreads();   // reads done; stid[cur^1] visible to all
        cur ^= 1;
    }

    // ragged tail (n % TPB elements), handled by block 0 straight from global
    if (blockIdx.x == 0) {
        int e = tiles_full * TPB + threadIdx.x;
        if (e < n) {
            float pr[PPE];
            const float* g = par + (size_t)e * PPE;
            #pragma unroll
            for (int i = 0; i < PPE; i++) pr[i] = g[i];
            lrs_compute(pr, inp[e], e, n, out);
        }
    }

    // ---- end-of-launch self-reset ----
    // Exact accounting: every CTA draws exactly one stop ticket (>= tiles_full),
    // so tickets per launch = tiles_full + gridDim.x. The LAST CTA to arrive
    // resets both counters for the next graph replay.
    __syncthreads();
    if (threadIdx.x == 0) {
        __threadfence();
        unsigned int d = atomicAdd(&g_done_ctr, 1u);
        if (d == gridDim.x - 1u) {
            atomicExch(&g_tile_ctr, 0u);
            atomicExch(&g_done_ctr, 0u);
        }
    }
}

extern "C" void kernel_launch(void* const* d_in, const int* in_sizes, int n_in,
                              void* d_out, int out_size) {
    const float* inp = (const float*)d_in[0];
    const float* par = (const float*)d_in[1];
    float* out = (float*)d_out;
    int n = in_sizes[0];

    cudaFuncSetAttribute(lrs_kernel, cudaFuncAttributeMaxDynamicSharedMemorySize, SMEM_BYTES);

    int ntiles = (n + TPB - 1) / TPB;
    int grid = GRID_CTAS < ntiles ? GRID_CTAS : (ntiles > 0 ? ntiles : 1);
    lrs_kernel<<<grid, TPB, SMEM_BYTES>>>(inp, par, out, n);
}